// round 16
// baseline (speedup 1.0000x reference)
#include <cuda_runtime.h>
#include <cuda_fp16.h>
#include <cstdint>

// Problem constants
#define NNODES 50000
#define NEDGES 800000
#define INDIM  128
#define HID    256
#define NGRAPH 128
#define NCLS   16

// ---------------- device scratch ----------------
__device__ __half g_bufH[NNODES * HID];    // messages (GEMM outputs)
__device__ __half g_bufAh[NNODES * HID];   // activations (gather outputs)
__device__ __half g_W2t[HID * HID];        // W2 transposed [n][k], fp16
__device__ float g_Wcomb[INDIM * HID];
__device__ float g_bcomb[HID];
__device__ float g_dinv[NNODES];
__device__ int   g_indeg[NNODES];
__device__ int   g_row_ptr[NNODES + 1];
__device__ int   g_epos[NEDGES];
__device__ int   g_csr_src[NEDGES];
__device__ int   g_localscan[NNODES];
__device__ int   g_blocksum[64];
__device__ int   g_is64;

__device__ __forceinline__ int get_idx(const void* p, int i, int is64) {
    if (is64) return (int)((const long long*)p)[i];
    return ((const int*)p)[i];
}

__device__ __forceinline__ void cp_async16(uint32_t saddr, const void* gptr) {
    asm volatile("cp.async.cg.shared.global [%0], [%1], 16;" :: "r"(saddr), "l"(gptr));
}
__device__ __forceinline__ void cp_commit() {
    asm volatile("cp.async.commit_group;");
}
template <int N>
__device__ __forceinline__ void cp_wait() {
    asm volatile("cp.async.wait_group %0;" :: "n"(N));
}

__device__ __forceinline__ uint32_t rna_tf32(uint32_t bits) {
    uint32_t u;
    asm("cvt.rna.tf32.f32 %0, %1;" : "=r"(u) : "f"(__uint_as_float(bits)));
    return u;
}

// acc[j] += scale * h16row[j]
__device__ __forceinline__ void fma_h16x8(float* acc, uint4 u, float scale) {
    const __half2* p = reinterpret_cast<const __half2*>(&u);
#pragma unroll
    for (int q = 0; q < 4; q++) {
        float2 f = __half22float2(p[q]);
        acc[2 * q]     = fmaf(f.x, scale, acc[2 * q]);
        acc[2 * q + 1] = fmaf(f.y, scale, acc[2 * q + 1]);
    }
}

// ---------------- weight folding: Wcomb = W_in @ W1, bcomb = b_in @ W1 (fp32) ----------------
__global__ void weight_combine_kernel(const float* __restrict__ Win, const float* __restrict__ bin,
                                      const float* __restrict__ W1,
                                      float* __restrict__ Wcomb, float* __restrict__ bcomb) {
    __shared__ float sRow[HID];
    int i = blockIdx.x;
    int j = threadIdx.x;
    const float* row = (i < INDIM) ? (Win + (size_t)i * HID) : bin;
    sRow[j] = row[j];
    __syncthreads();
    float s = 0.f;
    for (int k = 0; k < HID; k++) s = fmaf(sRow[k], W1[(size_t)k * HID + j], s);
    if (i < INDIM) Wcomb[(size_t)i * HID + j] = s;
    else bcomb[j] = s;
}

// ---------------- W2 transpose + fp16 convert: W2t[n][k] = half(W2[k][n]) ----------------
__global__ void transpose_w2_kernel(const float* __restrict__ W2, __half* __restrict__ W2t) {
    __shared__ float tile[32][33];
    int x = blockIdx.x * 32 + threadIdx.x;
    int y = blockIdx.y * 32 + threadIdx.y;
    tile[threadIdx.y][threadIdx.x] = W2[(size_t)y * HID + x];
    __syncthreads();
    int n = blockIdx.x * 32 + threadIdx.y;
    int k = blockIdx.y * 32 + threadIdx.x;
    W2t[(size_t)n * HID + k] = __float2half(tile[threadIdx.x][threadIdx.y]);
}

// ---------------- preprocessing ----------------
// hist: inline dtype detection; 2 edges/thread; records per-edge slot (epos).
__global__ void hist_dst_kernel(const void* __restrict__ ei, int E,
                                int* __restrict__ indeg, int* __restrict__ epos) {
    __shared__ int sFound;
    if (threadIdx.x == 0) sFound = 0;
    __syncthreads();
    {
        const int* w = (const int*)ei;
        int f = 0;
        for (int i = threadIdx.x; i < 1024; i += blockDim.x)
            if (w[2 * i + 1] != 0) f = 1;
        if (f) sFound = 1;
    }
    __syncthreads();
    const int is64 = sFound ? 0 : 1;
    if (blockIdx.x == 0 && threadIdx.x == 0) g_is64 = is64;

    int base = 2 * (blockIdx.x * blockDim.x + threadIdx.x);
#pragma unroll
    for (int q = 0; q < 2; q++) {
        int e = base + q;
        if (e < E) {
            int d = get_idx(ei, E + e, is64);
            epos[e] = atomicAdd(&indeg[d], 1);
        }
    }
}

__global__ void scan_local_kernel(const int* __restrict__ counts, int* __restrict__ localscan, int n) {
    __shared__ int s[1024];
    int tid = threadIdx.x;
    int i = blockIdx.x * 1024 + tid;
    int v = (i < n) ? counts[i] : 0;
    s[tid] = v;
    __syncthreads();
    for (int off = 1; off < 1024; off <<= 1) {
        int t = (tid >= off) ? s[tid - off] : 0;
        __syncthreads();
        s[tid] += t;
        __syncthreads();
    }
    if (i < n) localscan[i] = s[tid];
    if (tid == 1023) g_blocksum[blockIdx.x] = s[1023];
}

__global__ void scan_finalize_kernel(const int* __restrict__ counts, const int* __restrict__ localscan,
                                     int* __restrict__ row_ptr, float* __restrict__ dinv, int n) {
    __shared__ int sOff;
    int bucket = blockIdx.x >> 2;
    if (threadIdx.x == 0) {
        int off = 0;
        for (int j = 0; j < bucket; j++) off += g_blocksum[j];
        sOff = off;
    }
    __syncthreads();
    int i = blockIdx.x * blockDim.x + threadIdx.x;
    if (i < n) {
        int cnt = counts[i];
        int incl = localscan[i] + sOff;
        row_ptr[i + 1] = incl;
        dinv[i] = rsqrtf((float)cnt + 1.0f);
        if (i == 0) row_ptr[0] = 0;
    }
}

// atomic-free fill: slot already known from hist
__global__ void fill_csr_kernel(const void* __restrict__ ei, int E,
                                const int* __restrict__ row_ptr, const int* __restrict__ epos,
                                int* __restrict__ csr_src) {
    int e = blockIdx.x * blockDim.x + threadIdx.x;
    if (e < E) {
        int is64 = g_is64;
        int d = get_idx(ei, E + e, is64);
        int s = get_idx(ei, e, is64);
        csr_src[row_ptr[d] + epos[e]] = s;
    }
}

// ---------------- TF32 GEMM (input layer): persistent + cp.async ----------------
#define BM 128
#define BN 128
#define BK 16
#define AS_K 20
#define BS_N 136

__global__ __launch_bounds__(256, 2) void tf32gemm_kernel(
    const float* __restrict__ A, const float* __restrict__ B,
    __half* __restrict__ Ch,
    int M, int K, const float* __restrict__ bias) {
    __shared__ uint32_t As[2][BM * AS_K];
    __shared__ uint32_t Bs[2][BK * BS_N];

    const int tid = threadIdx.x;
    const int wid = tid >> 5;
    const int lane = tid & 31;
    const int warpM = wid & 3;
    const int warpN = wid >> 2;
    const int g = lane >> 2;
    const int t4 = lane & 3;
    const int mB = warpM * 32;
    const int nB = warpN * 64;

    const int aRow0 = tid >> 2;
    const int aRow1 = 64 + (tid >> 2);
    const int aC = (tid & 3) * 4;
    const int bRow0 = tid >> 5;
    const int bRow1 = 8 + (tid >> 5);
    const int bCol = (tid & 31) * 4;

    const uint32_t asBytes = BM * AS_K * 4;
    const uint32_t bsBytes = BK * BS_N * 4;
    const uint32_t sa0 = (uint32_t)__cvta_generic_to_shared(&As[0][aRow0 * AS_K + aC]);
    const uint32_t sa1 = (uint32_t)__cvta_generic_to_shared(&As[0][aRow1 * AS_K + aC]);
    const uint32_t sb0 = (uint32_t)__cvta_generic_to_shared(&Bs[0][bRow0 * BS_N + bCol]);
    const uint32_t sb1 = (uint32_t)__cvta_generic_to_shared(&Bs[0][bRow1 * BS_N + bCol]);

    const int nTiles = K / BK;
    const int numRowTiles = (M + BM - 1) / BM;
    const int numTiles = numRowTiles * (HID / BN);

    for (int bt = blockIdx.x; bt < numTiles; bt += gridDim.x) {
        const int rowBase = (bt >> 1) * BM;
        const int colBase = (bt & 1) * BN;

        int gr0 = rowBase + aRow0; gr0 = gr0 < M ? gr0 : M - 1;
        int gr1 = rowBase + aRow1; gr1 = gr1 < M ? gr1 : M - 1;
        const float* aPtr0 = A + (size_t)gr0 * K + aC;
        const float* aPtr1 = A + (size_t)gr1 * K + aC;
        const float* bPtr0 = B + (size_t)bRow0 * HID + colBase + bCol;
        const float* bPtr1 = B + (size_t)bRow1 * HID + colBase + bCol;

        float acc[2][8][4];
#pragma unroll
        for (int mt = 0; mt < 2; mt++)
#pragma unroll
            for (int nt = 0; nt < 8; nt++)
#pragma unroll
                for (int c = 0; c < 4; c++) acc[mt][nt][c] = 0.0f;

        cp_async16(sa0, aPtr0);
        cp_async16(sa1, aPtr1);
        cp_async16(sb0, bPtr0);
        cp_async16(sb1, bPtr1);
        cp_commit();
        if (nTiles > 1) {
            cp_async16(sa0 + asBytes, aPtr0 + BK);
            cp_async16(sa1 + asBytes, aPtr1 + BK);
            cp_async16(sb0 + bsBytes, bPtr0 + (size_t)BK * HID);
            cp_async16(sb1 + bsBytes, bPtr1 + (size_t)BK * HID);
            cp_commit();
        }

        for (int t = 0; t < nTiles; t++) {
            if (t + 1 < nTiles) cp_wait<1>(); else cp_wait<0>();
            __syncthreads();

            const int st = t & 1;
            const uint32_t* AsS = As[st];
            const uint32_t* BsS = Bs[st];

#pragma unroll
            for (int ks = 0; ks < BK; ks += 8) {
                uint32_t af[2][4];
#pragma unroll
                for (int mt = 0; mt < 2; mt++) {
                    int m0 = mB + mt * 16 + g;
                    af[mt][0] = rna_tf32(AsS[m0 * AS_K + ks + t4]);
                    af[mt][1] = rna_tf32(AsS[(m0 + 8) * AS_K + ks + t4]);
                    af[mt][2] = rna_tf32(AsS[m0 * AS_K + ks + t4 + 4]);
                    af[mt][3] = rna_tf32(AsS[(m0 + 8) * AS_K + ks + t4 + 4]);
                }
                uint32_t bf[8][2];
#pragma unroll
                for (int nt = 0; nt < 8; nt++) {
                    int n0 = nB + nt * 8 + g;
                    bf[nt][0] = rna_tf32(BsS[(ks + t4) * BS_N + n0]);
                    bf[nt][1] = rna_tf32(BsS[(ks + t4 + 4) * BS_N + n0]);
                }
#pragma unroll
                for (int mt = 0; mt < 2; mt++)
#pragma unroll
                    for (int nt = 0; nt < 8; nt++) {
                        asm volatile(
                            "mma.sync.aligned.m16n8k8.row.col.f32.tf32.tf32.f32 "
                            "{%0,%1,%2,%3}, {%4,%5,%6,%7}, {%8,%9}, {%0,%1,%2,%3};"
                            : "+f"(acc[mt][nt][0]), "+f"(acc[mt][nt][1]),
                              "+f"(acc[mt][nt][2]), "+f"(acc[mt][nt][3])
                            : "r"(af[mt][0]), "r"(af[mt][1]), "r"(af[mt][2]), "r"(af[mt][3]),
                              "r"(bf[nt][0]), "r"(bf[nt][1]));
                    }
            }
            __syncthreads();

            if (t + 2 < nTiles) {
                int k0 = (t + 2) * BK;
                uint32_t off = st ? asBytes : 0;
                uint32_t offB = st ? bsBytes : 0;
                cp_async16(sa0 + off, aPtr0 + k0);
                cp_async16(sa1 + off, aPtr1 + k0);
                cp_async16(sb0 + offB, bPtr0 + (size_t)k0 * HID);
                cp_async16(sb1 + offB, bPtr1 + (size_t)k0 * HID);
                cp_commit();
            }
        }

#pragma unroll
        for (int mt = 0; mt < 2; mt++) {
            int r0 = rowBase + mB + mt * 16 + g;
            int r1 = r0 + 8;
#pragma unroll
            for (int nt = 0; nt < 8; nt++) {
                int c = colBase + nB + nt * 8 + t4 * 2;
                float bx = 0.f, by = 0.f;
                if (bias) { bx = bias[c]; by = bias[c + 1]; }
                if (r0 < M) {
                    __half2 p = __floats2half2_rn(acc[mt][nt][0] + bx, acc[mt][nt][1] + by);
                    *reinterpret_cast<__half2*>(&Ch[(size_t)r0 * HID + c]) = p;
                }
                if (r1 < M) {
                    __half2 p = __floats2half2_rn(acc[mt][nt][2] + bx, acc[mt][nt][3] + by);
                    *reinterpret_cast<__half2*>(&Ch[(size_t)r1 * HID + c]) = p;
                }
            }
        }
        __syncthreads();
    }
}

// ---------------- FP16 GEMM (layer 2) ----------------
#define HS 12

__global__ __launch_bounds__(256, 2) void f16gemm_kernel(
    const __half* __restrict__ A, const __half* __restrict__ Bt,
    __half* __restrict__ Ch, int M) {
    __shared__ uint32_t As[2][BM * HS];
    __shared__ uint32_t Bs[2][BN * HS];

    const int tid = threadIdx.x;
    const int wid = tid >> 5;
    const int lane = tid & 31;
    const int warpM = wid & 3;
    const int warpN = wid >> 2;
    const int g = lane >> 2;
    const int t4 = lane & 3;
    const int mB = warpM * 32;
    const int nB = warpN * 64;

    const int ldRow = tid >> 1;
    const int ldHalf = tid & 1;

    const uint32_t asBytes = BM * HS * 4;
    const uint32_t bsBytes = BN * HS * 4;
    const uint32_t sa = (uint32_t)__cvta_generic_to_shared(&As[0][ldRow * HS + ldHalf * 4]);
    const uint32_t sb = (uint32_t)__cvta_generic_to_shared(&Bs[0][ldRow * HS + ldHalf * 4]);

    const int K = HID;
    const int nTiles = K / BK;
    const int numRowTiles = (M + BM - 1) / BM;
    const int numTiles = numRowTiles * (HID / BN);

    for (int bt = blockIdx.x; bt < numTiles; bt += gridDim.x) {
        const int rowBase = (bt >> 1) * BM;
        const int colBase = (bt & 1) * BN;

        int gr = rowBase + ldRow; gr = gr < M ? gr : M - 1;
        const __half* aPtr = A + (size_t)gr * K + ldHalf * 8;
        const __half* bPtr = Bt + (size_t)(colBase + ldRow) * K + ldHalf * 8;

        float acc[2][8][4];
#pragma unroll
        for (int mt = 0; mt < 2; mt++)
#pragma unroll
            for (int nt = 0; nt < 8; nt++)
#pragma unroll
                for (int c = 0; c < 4; c++) acc[mt][nt][c] = 0.0f;

        cp_async16(sa, aPtr);
        cp_async16(sb, bPtr);
        cp_commit();
        cp_async16(sa + asBytes, aPtr + BK);
        cp_async16(sb + bsBytes, bPtr + BK);
        cp_commit();

        for (int t = 0; t < nTiles; t++) {
            if (t + 1 < nTiles) cp_wait<1>(); else cp_wait<0>();
            __syncthreads();

            const int st = t & 1;
            const uint32_t* AsS = As[st];
            const uint32_t* BsS = Bs[st];

            uint32_t af[2][4];
#pragma unroll
            for (int mt = 0; mt < 2; mt++) {
                int m0 = mB + mt * 16 + g;
                af[mt][0] = AsS[m0 * HS + t4];
                af[mt][1] = AsS[(m0 + 8) * HS + t4];
                af[mt][2] = AsS[m0 * HS + t4 + 4];
                af[mt][3] = AsS[(m0 + 8) * HS + t4 + 4];
            }
            uint32_t bf[8][2];
#pragma unroll
            for (int nt = 0; nt < 8; nt++) {
                int n0 = nB + nt * 8 + g;
                bf[nt][0] = BsS[n0 * HS + t4];
                bf[nt][1] = BsS[n0 * HS + t4 + 4];
            }
#pragma unroll
            for (int mt = 0; mt < 2; mt++)
#pragma unroll
                for (int nt = 0; nt < 8; nt++) {
                    asm volatile(
                        "mma.sync.aligned.m16n8k16.row.col.f32.f16.f16.f32 "
                        "{%0,%1,%2,%3}, {%4,%5,%6,%7}, {%8,%9}, {%0,%1,%2,%3};"
                        : "+f"(acc[mt][nt][0]), "+f"(acc[mt][nt][1]),
                          "+f"(acc[mt][nt][2]), "+f"(acc[mt][nt][3])
                        : "r"(af[mt][0]), "r"(af[mt][1]), "r"(af[mt][2]), "r"(af[mt][3]),
                          "r"(bf[nt][0]), "r"(bf[nt][1]));
                }
            __syncthreads();

            if (t + 2 < nTiles) {
                int k0 = (t + 2) * BK;
                uint32_t off = st ? asBytes : 0;
                uint32_t offB = st ? bsBytes : 0;
                cp_async16(sa + off, aPtr + k0);
                cp_async16(sb + offB, bPtr + k0);
                cp_commit();
            }
        }

#pragma unroll
        for (int mt = 0; mt < 2; mt++) {
            int r0 = rowBase + mB + mt * 16 + g;
            int r1 = r0 + 8;
#pragma unroll
            for (int nt = 0; nt < 8; nt++) {
                int c = colBase + nB + nt * 8 + t4 * 2;
                if (r0 < M) {
                    __half2 p = __floats2half2_rn(acc[mt][nt][0], acc[mt][nt][1]);
                    *reinterpret_cast<__half2*>(&Ch[(size_t)r0 * HID + c]) = p;
                }
                if (r1 < M) {
                    __half2 p = __floats2half2_rn(acc[mt][nt][2], acc[mt][nt][3]);
                    *reinterpret_cast<__half2*>(&Ch[(size_t)r1 * HID + c]) = p;
                }
            }
        }
        __syncthreads();
    }
}

// ---------------- gather: fp16 in, fp16 out ----------------
__global__ void gather_kernel(const __half* __restrict__ hp, __half* __restrict__ out,
                              const int* __restrict__ row_ptr, const int* __restrict__ csr_src,
                              const float* __restrict__ dinv, const float* __restrict__ bias, int n) {
    int warp = (blockIdx.x * blockDim.x + threadIdx.x) >> 5;
    int lane = threadIdx.x & 31;
    if (warp >= n) return;
    int beg = row_ptr[warp];
    int end = row_ptr[warp + 1];
    const int colOff = lane * 8;

    float a0[8], a1[8];
#pragma unroll
    for (int j = 0; j < 8; j++) { a0[j] = 0.f; a1[j] = 0.f; }

    int e = beg;
    for (; e + 8 <= end; e += 8) {
        int s[8];
#pragma unroll
        for (int q = 0; q < 8; q++) s[q] = csr_src[e + q];
        uint4 u[8];
        float dv[8];
#pragma unroll
        for (int q = 0; q < 8; q++) {
            u[q] = __ldg(reinterpret_cast<const uint4*>(hp + (size_t)s[q] * HID + colOff));
            dv[q] = __ldg(&dinv[s[q]]);
        }
#pragma unroll
        for (int q = 0; q < 8; q++) fma_h16x8((q & 1) ? a1 : a0, u[q], dv[q]);
    }
    if (e + 4 <= end) {
        int s[4];
#pragma unroll
        for (int q = 0; q < 4; q++) s[q] = csr_src[e + q];
        uint4 u[4];
        float dv[4];
#pragma unroll
        for (int q = 0; q < 4; q++) {
            u[q] = __ldg(reinterpret_cast<const uint4*>(hp + (size_t)s[q] * HID + colOff));
            dv[q] = __ldg(&dinv[s[q]]);
        }
#pragma unroll
        for (int q = 0; q < 4; q++) fma_h16x8((q & 1) ? a1 : a0, u[q], dv[q]);
        e += 4;
    }
    for (; e < end; e++) {
        int s = csr_src[e];
        uint4 u = __ldg(reinterpret_cast<const uint4*>(hp + (size_t)s * HID + colOff));
        float dv = __ldg(&dinv[s]);
        fma_h16x8(a0, u, dv);
    }

    float dvd = dinv[warp];
    {
        uint4 u = *reinterpret_cast<const uint4*>(hp + (size_t)warp * HID + colOff);
        fma_h16x8(a1, u, dvd);
    }

    float4 b0 = *reinterpret_cast<const float4*>(bias + colOff);
    float4 b1 = *reinterpret_cast<const float4*>(bias + colOff + 4);
    float o[8];
    o[0] = fmaxf(dvd * (a0[0] + a1[0]) + b0.x, 0.f);
    o[1] = fmaxf(dvd * (a0[1] + a1[1]) + b0.y, 0.f);
    o[2] = fmaxf(dvd * (a0[2] + a1[2]) + b0.z, 0.f);
    o[3] = fmaxf(dvd * (a0[3] + a1[3]) + b0.w, 0.f);
    o[4] = fmaxf(dvd * (a0[4] + a1[4]) + b1.x, 0.f);
    o[5] = fmaxf(dvd * (a0[5] + a1[5]) + b1.y, 0.f);
    o[6] = fmaxf(dvd * (a0[6] + a1[6]) + b1.z, 0.f);
    o[7] = fmaxf(dvd * (a0[7] + a1[7]) + b1.w, 0.f);

    uint4 packed;
    uint32_t* pw = reinterpret_cast<uint32_t*>(&packed);
#pragma unroll
    for (int q = 0; q < 4; q++) {
        __half2 p = __floats2half2_rn(o[2 * q], o[2 * q + 1]);
        pw[q] = *reinterpret_cast<uint32_t*>(&p);
    }
    *reinterpret_cast<uint4*>(out + (size_t)warp * HID + colOff) = packed;
}

// ---------------- fused pooling + output head (fp16 input) ----------------
__global__ void pool_out_kernel(const __half* __restrict__ h, const void* __restrict__ batch,
                                int n, const float* __restrict__ W, const float* __restrict__ b,
                                float* __restrict__ out) {
    __shared__ int sRange[2];
    __shared__ float sPool[HID];
    int g = blockIdx.x;
    int tid = threadIdx.x;
    if (tid < 2) {
        int target = g + tid;
        int is64 = g_is64;
        int lo = 0, hi = n;
        while (lo < hi) {
            int mid = (lo + hi) >> 1;
            if (get_idx(batch, mid, is64) < target) lo = mid + 1; else hi = mid;
        }
        sRange[tid] = lo;
    }
    __syncthreads();
    int beg = sRange[0];
    int end = sRange[1];
    float sum = 0.0f;
    for (int i = beg; i < end; i++) sum += __half2float(h[(size_t)i * HID + tid]);
    sPool[tid] = sum / fmaxf((float)(end - beg), 1.0f);
    __syncthreads();

    {
        int c = tid & 15;
        int k0 = (tid >> 4) * 16;
        float p = 0.0f;
#pragma unroll
        for (int k = 0; k < 16; k++) p += sPool[k0 + k] * W[(k0 + k) * NCLS + c];
        __shared__ float sAll[16][NCLS];
        sAll[tid >> 4][c] = p;
        __syncthreads();
        if (tid < NCLS) {
            float s = b[tid];
#pragma unroll
            for (int q = 0; q < 16; q++) s += sAll[q][tid];
            out[g * NCLS + tid] = s;
        }
    }
}

// ---------------- launch ----------------
extern "C" void kernel_launch(void* const* d_in, const int* in_sizes, int n_in,
                              void* d_out, int out_size) {
    const float* x     = (const float*)d_in[0];
    const void*  ei    = d_in[1];
    const void*  batch = d_in[2];
    const float* W_in  = (const float*)d_in[3];
    const float* b_in  = (const float*)d_in[4];
    const float* W1    = (const float*)d_in[5];
    const float* b1    = (const float*)d_in[6];
    const float* W2    = (const float*)d_in[7];
    const float* b2    = (const float*)d_in[8];
    const float* W_out = (const float*)d_in[9];
    const float* b_out = (const float*)d_in[10];

    const int N = in_sizes[0] / INDIM;
    const int E = in_sizes[1] / 2;

    float *dinv, *Wcomb, *bcomb;
    __half *bufH, *bufAh, *W2t;
    int *indeg, *row_ptr, *epos, *csr_src, *localscan;
    cudaGetSymbolAddress((void**)&bufH, g_bufH);
    cudaGetSymbolAddress((void**)&bufAh, g_bufAh);
    cudaGetSymbolAddress((void**)&W2t, g_W2t);
    cudaGetSymbolAddress((void**)&Wcomb, g_Wcomb);
    cudaGetSymbolAddress((void**)&bcomb, g_bcomb);
    cudaGetSymbolAddress((void**)&dinv, g_dinv);
    cudaGetSymbolAddress((void**)&indeg, g_indeg);
    cudaGetSymbolAddress((void**)&row_ptr, g_row_ptr);
    cudaGetSymbolAddress((void**)&epos, g_epos);
    cudaGetSymbolAddress((void**)&csr_src, g_csr_src);
    cudaGetSymbolAddress((void**)&localscan, g_localscan);

    static cudaStream_t sSide = nullptr;
    static cudaEvent_t evFork = nullptr, evJoin = nullptr;
    if (sSide == nullptr) {
        cudaStreamCreateWithFlags(&sSide, cudaStreamNonBlocking);
        cudaEventCreateWithFlags(&evFork, cudaEventDisableTiming);
        cudaEventCreateWithFlags(&evJoin, cudaEventDisableTiming);
    }

    const int GEMM_GRID = 296;

    // ---- fork: preprocessing on side stream ----
    cudaEventRecord(evFork, 0);
    cudaStreamWaitEvent(sSide, evFork, 0);

    cudaMemsetAsync(indeg, 0, N * sizeof(int), sSide);
    hist_dst_kernel<<<(E / 2 + 255) / 256, 256, 0, sSide>>>(ei, E, indeg, epos);
    const int nb = (N + 1023) / 1024;
    scan_local_kernel<<<nb, 1024, 0, sSide>>>(indeg, localscan, N);
    scan_finalize_kernel<<<(N + 255) / 256, 256, 0, sSide>>>(indeg, localscan, row_ptr, dinv, N);
    fill_csr_kernel<<<(E + 255) / 256, 256, 0, sSide>>>(ei, E, row_ptr, epos, csr_src);
    cudaEventRecord(evJoin, sSide);

    // ---- main stream ----
    {
        dim3 tb(32, 32);
        dim3 tg(HID / 32, HID / 32);
        transpose_w2_kernel<<<tg, tb>>>(W2, W2t);
    }
    weight_combine_kernel<<<INDIM + 1, HID>>>(W_in, b_in, W1, Wcomb, bcomb);
    tf32gemm_kernel<<<GEMM_GRID, 256>>>(x, Wcomb, bufH, N, INDIM, bcomb);

    cudaStreamWaitEvent(0, evJoin, 0);

    gather_kernel<<<(N * 32 + 255) / 256, 256>>>(bufH, bufAh, row_ptr, csr_src, dinv, b1, N);
    f16gemm_kernel<<<GEMM_GRID, 256>>>(bufAh, W2t, bufH, N);
    gather_kernel<<<(N * 32 + 255) / 256, 256>>>(bufH, bufAh, row_ptr, csr_src, dinv, b2, N);

    pool_out_kernel<<<NGRAPH, HID>>>(bufAh, batch, N, W_out, b_out, (float*)d_out);
}

// round 17
// speedup vs baseline: 1.0590x; 1.0590x over previous
#include <cuda_runtime.h>
#include <cuda_fp16.h>
#include <cstdint>

// Problem constants
#define NNODES 50000
#define NEDGES 800000
#define INDIM  128
#define HID    256
#define NGRAPH 128
#define NCLS   16

// ---------------- device scratch ----------------
__device__ __half g_bufH[NNODES * HID];    // messages (pre-scaled by dinv[src])
__device__ __half g_bufAh[NNODES * HID];   // activations (gather outputs)
__device__ __half g_W2t[HID * HID];        // W2 transposed [n][k], fp16
__device__ float g_Wcomb[INDIM * HID];
__device__ float g_bcomb[HID];
__device__ float g_dinv[NNODES];
__device__ int   g_indeg[NNODES];
__device__ int   g_row_ptr[NNODES + 1];
__device__ int   g_cursor[NNODES];
__device__ int   g_csr_src[NEDGES];
__device__ int   g_localscan[NNODES];
__device__ int   g_blocksum[64];
__device__ int   g_is64;

__device__ __forceinline__ int get_idx(const void* p, int i, int is64) {
    if (is64) return (int)((const long long*)p)[i];
    return ((const int*)p)[i];
}

__device__ __forceinline__ void cp_async16(uint32_t saddr, const void* gptr) {
    asm volatile("cp.async.cg.shared.global [%0], [%1], 16;" :: "r"(saddr), "l"(gptr));
}
__device__ __forceinline__ void cp_commit() {
    asm volatile("cp.async.commit_group;");
}
template <int N>
__device__ __forceinline__ void cp_wait() {
    asm volatile("cp.async.wait_group %0;" :: "n"(N));
}

__device__ __forceinline__ uint32_t rna_tf32(uint32_t bits) {
    uint32_t u;
    asm("cvt.rna.tf32.f32 %0, %1;" : "=r"(u) : "f"(__uint_as_float(bits)));
    return u;
}

// acc[j] += h16row[j]
__device__ __forceinline__ void add_h16x8(float* acc, uint4 u) {
    const __half2* p = reinterpret_cast<const __half2*>(&u);
#pragma unroll
    for (int q = 0; q < 4; q++) {
        float2 f = __half22float2(p[q]);
        acc[2 * q]     += f.x;
        acc[2 * q + 1] += f.y;
    }
}

// ---------------- weight folding: Wcomb = W_in @ W1, bcomb = b_in @ W1 (fp32) ----------------
__global__ void weight_combine_kernel(const float* __restrict__ Win, const float* __restrict__ bin,
                                      const float* __restrict__ W1,
                                      float* __restrict__ Wcomb, float* __restrict__ bcomb) {
    __shared__ float sRow[HID];
    int i = blockIdx.x;
    int j = threadIdx.x;
    const float* row = (i < INDIM) ? (Win + (size_t)i * HID) : bin;
    sRow[j] = row[j];
    __syncthreads();
    float s = 0.f;
    for (int k = 0; k < HID; k++) s = fmaf(sRow[k], W1[(size_t)k * HID + j], s);
    if (i < INDIM) Wcomb[(size_t)i * HID + j] = s;
    else bcomb[j] = s;
}

// ---------------- W2 transpose + fp16 convert ----------------
__global__ void transpose_w2_kernel(const float* __restrict__ W2, __half* __restrict__ W2t) {
    __shared__ float tile[32][33];
    int x = blockIdx.x * 32 + threadIdx.x;
    int y = blockIdx.y * 32 + threadIdx.y;
    tile[threadIdx.y][threadIdx.x] = W2[(size_t)y * HID + x];
    __syncthreads();
    int n = blockIdx.x * 32 + threadIdx.y;
    int k = blockIdx.y * 32 + threadIdx.x;
    W2t[(size_t)n * HID + k] = __float2half(tile[threadIdx.x][threadIdx.y]);
}

// ---------------- preprocessing (R15 cursor scheme + inline detect) ----------------
__global__ void hist_dst_kernel(const void* __restrict__ ei, int E, int* __restrict__ indeg) {
    __shared__ int sFound;
    if (threadIdx.x == 0) sFound = 0;
    __syncthreads();
    {
        const int* w = (const int*)ei;
        int f = 0;
        for (int i = threadIdx.x; i < 1024; i += blockDim.x)
            if (w[2 * i + 1] != 0) f = 1;
        if (f) sFound = 1;
    }
    __syncthreads();
    const int is64 = sFound ? 0 : 1;
    if (blockIdx.x == 0 && threadIdx.x == 0) g_is64 = is64;

    int e = blockIdx.x * blockDim.x + threadIdx.x;
    if (e < E) {
        int d = get_idx(ei, E + e, is64);
        atomicAdd(&indeg[d], 1);
    }
}

__global__ void scan_local_kernel(const int* __restrict__ counts, int* __restrict__ localscan, int n) {
    __shared__ int s[1024];
    int tid = threadIdx.x;
    int i = blockIdx.x * 1024 + tid;
    int v = (i < n) ? counts[i] : 0;
    s[tid] = v;
    __syncthreads();
    for (int off = 1; off < 1024; off <<= 1) {
        int t = (tid >= off) ? s[tid - off] : 0;
        __syncthreads();
        s[tid] += t;
        __syncthreads();
    }
    if (i < n) localscan[i] = s[tid];
    if (tid == 1023) g_blocksum[blockIdx.x] = s[1023];
}

__global__ void scan_finalize_kernel(const int* __restrict__ counts, const int* __restrict__ localscan,
                                     int* __restrict__ row_ptr, int* __restrict__ cursor,
                                     float* __restrict__ dinv, int n) {
    __shared__ int sOff;
    int bucket = blockIdx.x >> 2;
    if (threadIdx.x == 0) {
        int off = 0;
        for (int j = 0; j < bucket; j++) off += g_blocksum[j];
        sOff = off;
    }
    __syncthreads();
    int i = blockIdx.x * blockDim.x + threadIdx.x;
    if (i < n) {
        int cnt = counts[i];
        int incl = localscan[i] + sOff;
        row_ptr[i + 1] = incl;
        cursor[i] = incl - cnt;
        dinv[i] = rsqrtf((float)cnt + 1.0f);
        if (i == 0) row_ptr[0] = 0;
    }
}

__global__ void fill_csr_kernel(const void* __restrict__ ei, int E,
                                int* __restrict__ cursor, int* __restrict__ csr_src) {
    int e = blockIdx.x * blockDim.x + threadIdx.x;
    if (e < E) {
        int is64 = g_is64;
        int d = get_idx(ei, E + e, is64);
        int s = get_idx(ei, e, is64);
        int pos = atomicAdd(&cursor[d], 1);
        csr_src[pos] = s;
    }
}

// ---------------- scale rows: bufH[i,:] *= dinv[i] (fp16 in/out) ----------------
__global__ void scale_rows_kernel(__half* __restrict__ h, const float* __restrict__ dinv, int n) {
    int idx = blockIdx.x * blockDim.x + threadIdx.x;   // one thread = 8 fp16
    int total = n * (HID / 8);
    if (idx >= total) return;
    int r = idx / (HID / 8);
    float dv = dinv[r];
    uint4 u = *reinterpret_cast<const uint4*>(h + (size_t)idx * 8);
    __half2* p = reinterpret_cast<__half2*>(&u);
#pragma unroll
    for (int q = 0; q < 4; q++) {
        float2 f = __half22float2(p[q]);
        p[q] = __floats2half2_rn(f.x * dv, f.y * dv);
    }
    *reinterpret_cast<uint4*>(h + (size_t)idx * 8) = u;
}

// ---------------- TF32 GEMM (input layer): persistent + cp.async ----------------
#define BM 128
#define BN 128
#define BK 16
#define AS_K 20
#define BS_N 136

__global__ __launch_bounds__(256, 2) void tf32gemm_kernel(
    const float* __restrict__ A, const float* __restrict__ B,
    __half* __restrict__ Ch,
    int M, int K, const float* __restrict__ bias) {
    __shared__ uint32_t As[2][BM * AS_K];
    __shared__ uint32_t Bs[2][BK * BS_N];

    const int tid = threadIdx.x;
    const int wid = tid >> 5;
    const int lane = tid & 31;
    const int warpM = wid & 3;
    const int warpN = wid >> 2;
    const int g = lane >> 2;
    const int t4 = lane & 3;
    const int mB = warpM * 32;
    const int nB = warpN * 64;

    const int aRow0 = tid >> 2;
    const int aRow1 = 64 + (tid >> 2);
    const int aC = (tid & 3) * 4;
    const int bRow0 = tid >> 5;
    const int bRow1 = 8 + (tid >> 5);
    const int bCol = (tid & 31) * 4;

    const uint32_t asBytes = BM * AS_K * 4;
    const uint32_t bsBytes = BK * BS_N * 4;
    const uint32_t sa0 = (uint32_t)__cvta_generic_to_shared(&As[0][aRow0 * AS_K + aC]);
    const uint32_t sa1 = (uint32_t)__cvta_generic_to_shared(&As[0][aRow1 * AS_K + aC]);
    const uint32_t sb0 = (uint32_t)__cvta_generic_to_shared(&Bs[0][bRow0 * BS_N + bCol]);
    const uint32_t sb1 = (uint32_t)__cvta_generic_to_shared(&Bs[0][bRow1 * BS_N + bCol]);

    const int nTiles = K / BK;
    const int numRowTiles = (M + BM - 1) / BM;
    const int numTiles = numRowTiles * (HID / BN);

    for (int bt = blockIdx.x; bt < numTiles; bt += gridDim.x) {
        const int rowBase = (bt >> 1) * BM;
        const int colBase = (bt & 1) * BN;

        int gr0 = rowBase + aRow0; gr0 = gr0 < M ? gr0 : M - 1;
        int gr1 = rowBase + aRow1; gr1 = gr1 < M ? gr1 : M - 1;
        const float* aPtr0 = A + (size_t)gr0 * K + aC;
        const float* aPtr1 = A + (size_t)gr1 * K + aC;
        const float* bPtr0 = B + (size_t)bRow0 * HID + colBase + bCol;
        const float* bPtr1 = B + (size_t)bRow1 * HID + colBase + bCol;

        float acc[2][8][4];
#pragma unroll
        for (int mt = 0; mt < 2; mt++)
#pragma unroll
            for (int nt = 0; nt < 8; nt++)
#pragma unroll
                for (int c = 0; c < 4; c++) acc[mt][nt][c] = 0.0f;

        cp_async16(sa0, aPtr0);
        cp_async16(sa1, aPtr1);
        cp_async16(sb0, bPtr0);
        cp_async16(sb1, bPtr1);
        cp_commit();
        if (nTiles > 1) {
            cp_async16(sa0 + asBytes, aPtr0 + BK);
            cp_async16(sa1 + asBytes, aPtr1 + BK);
            cp_async16(sb0 + bsBytes, bPtr0 + (size_t)BK * HID);
            cp_async16(sb1 + bsBytes, bPtr1 + (size_t)BK * HID);
            cp_commit();
        }

        for (int t = 0; t < nTiles; t++) {
            if (t + 1 < nTiles) cp_wait<1>(); else cp_wait<0>();
            __syncthreads();

            const int st = t & 1;
            const uint32_t* AsS = As[st];
            const uint32_t* BsS = Bs[st];

#pragma unroll
            for (int ks = 0; ks < BK; ks += 8) {
                uint32_t af[2][4];
#pragma unroll
                for (int mt = 0; mt < 2; mt++) {
                    int m0 = mB + mt * 16 + g;
                    af[mt][0] = rna_tf32(AsS[m0 * AS_K + ks + t4]);
                    af[mt][1] = rna_tf32(AsS[(m0 + 8) * AS_K + ks + t4]);
                    af[mt][2] = rna_tf32(AsS[m0 * AS_K + ks + t4 + 4]);
                    af[mt][3] = rna_tf32(AsS[(m0 + 8) * AS_K + ks + t4 + 4]);
                }
                uint32_t bf[8][2];
#pragma unroll
                for (int nt = 0; nt < 8; nt++) {
                    int n0 = nB + nt * 8 + g;
                    bf[nt][0] = rna_tf32(BsS[(ks + t4) * BS_N + n0]);
                    bf[nt][1] = rna_tf32(BsS[(ks + t4 + 4) * BS_N + n0]);
                }
#pragma unroll
                for (int mt = 0; mt < 2; mt++)
#pragma unroll
                    for (int nt = 0; nt < 8; nt++) {
                        asm volatile(
                            "mma.sync.aligned.m16n8k8.row.col.f32.tf32.tf32.f32 "
                            "{%0,%1,%2,%3}, {%4,%5,%6,%7}, {%8,%9}, {%0,%1,%2,%3};"
                            : "+f"(acc[mt][nt][0]), "+f"(acc[mt][nt][1]),
                              "+f"(acc[mt][nt][2]), "+f"(acc[mt][nt][3])
                            : "r"(af[mt][0]), "r"(af[mt][1]), "r"(af[mt][2]), "r"(af[mt][3]),
                              "r"(bf[nt][0]), "r"(bf[nt][1]));
                    }
            }
            __syncthreads();

            if (t + 2 < nTiles) {
                int k0 = (t + 2) * BK;
                uint32_t off = st ? asBytes : 0;
                uint32_t offB = st ? bsBytes : 0;
                cp_async16(sa0 + off, aPtr0 + k0);
                cp_async16(sa1 + off, aPtr1 + k0);
                cp_async16(sb0 + offB, bPtr0 + (size_t)k0 * HID);
                cp_async16(sb1 + offB, bPtr1 + (size_t)k0 * HID);
                cp_commit();
            }
        }

#pragma unroll
        for (int mt = 0; mt < 2; mt++) {
            int r0 = rowBase + mB + mt * 16 + g;
            int r1 = r0 + 8;
#pragma unroll
            for (int nt = 0; nt < 8; nt++) {
                int c = colBase + nB + nt * 8 + t4 * 2;
                float bx = 0.f, by = 0.f;
                if (bias) { bx = bias[c]; by = bias[c + 1]; }
                if (r0 < M) {
                    __half2 p = __floats2half2_rn(acc[mt][nt][0] + bx, acc[mt][nt][1] + by);
                    *reinterpret_cast<__half2*>(&Ch[(size_t)r0 * HID + c]) = p;
                }
                if (r1 < M) {
                    __half2 p = __floats2half2_rn(acc[mt][nt][2] + bx, acc[mt][nt][3] + by);
                    *reinterpret_cast<__half2*>(&Ch[(size_t)r1 * HID + c]) = p;
                }
            }
        }
        __syncthreads();
    }
}

// ---------------- FP16 GEMM (layer 2), epilogue row-scale by dinv ----------------
#define HS 12

__global__ __launch_bounds__(256, 2) void f16gemm_kernel(
    const __half* __restrict__ A, const __half* __restrict__ Bt,
    __half* __restrict__ Ch, int M, const float* __restrict__ scale) {
    __shared__ uint32_t As[2][BM * HS];
    __shared__ uint32_t Bs[2][BN * HS];

    const int tid = threadIdx.x;
    const int wid = tid >> 5;
    const int lane = tid & 31;
    const int warpM = wid & 3;
    const int warpN = wid >> 2;
    const int g = lane >> 2;
    const int t4 = lane & 3;
    const int mB = warpM * 32;
    const int nB = warpN * 64;

    const int ldRow = tid >> 1;
    const int ldHalf = tid & 1;

    const uint32_t asBytes = BM * HS * 4;
    const uint32_t bsBytes = BN * HS * 4;
    const uint32_t sa = (uint32_t)__cvta_generic_to_shared(&As[0][ldRow * HS + ldHalf * 4]);
    const uint32_t sb = (uint32_t)__cvta_generic_to_shared(&Bs[0][ldRow * HS + ldHalf * 4]);

    const int K = HID;
    const int nTiles = K / BK;
    const int numRowTiles = (M + BM - 1) / BM;
    const int numTiles = numRowTiles * (HID / BN);

    for (int bt = blockIdx.x; bt < numTiles; bt += gridDim.x) {
        const int rowBase = (bt >> 1) * BM;
        const int colBase = (bt & 1) * BN;

        int gr = rowBase + ldRow; gr = gr < M ? gr : M - 1;
        const __half* aPtr = A + (size_t)gr * K + ldHalf * 8;
        const __half* bPtr = Bt + (size_t)(colBase + ldRow) * K + ldHalf * 8;

        float acc[2][8][4];
#pragma unroll
        for (int mt = 0; mt < 2; mt++)
#pragma unroll
            for (int nt = 0; nt < 8; nt++)
#pragma unroll
                for (int c = 0; c < 4; c++) acc[mt][nt][c] = 0.0f;

        cp_async16(sa, aPtr);
        cp_async16(sb, bPtr);
        cp_commit();
        cp_async16(sa + asBytes, aPtr + BK);
        cp_async16(sb + bsBytes, bPtr + BK);
        cp_commit();

        for (int t = 0; t < nTiles; t++) {
            if (t + 1 < nTiles) cp_wait<1>(); else cp_wait<0>();
            __syncthreads();

            const int st = t & 1;
            const uint32_t* AsS = As[st];
            const uint32_t* BsS = Bs[st];

            uint32_t af[2][4];
#pragma unroll
            for (int mt = 0; mt < 2; mt++) {
                int m0 = mB + mt * 16 + g;
                af[mt][0] = AsS[m0 * HS + t4];
                af[mt][1] = AsS[(m0 + 8) * HS + t4];
                af[mt][2] = AsS[m0 * HS + t4 + 4];
                af[mt][3] = AsS[(m0 + 8) * HS + t4 + 4];
            }
            uint32_t bf[8][2];
#pragma unroll
            for (int nt = 0; nt < 8; nt++) {
                int n0 = nB + nt * 8 + g;
                bf[nt][0] = BsS[n0 * HS + t4];
                bf[nt][1] = BsS[n0 * HS + t4 + 4];
            }
#pragma unroll
            for (int mt = 0; mt < 2; mt++)
#pragma unroll
                for (int nt = 0; nt < 8; nt++) {
                    asm volatile(
                        "mma.sync.aligned.m16n8k16.row.col.f32.f16.f16.f32 "
                        "{%0,%1,%2,%3}, {%4,%5,%6,%7}, {%8,%9}, {%0,%1,%2,%3};"
                        : "+f"(acc[mt][nt][0]), "+f"(acc[mt][nt][1]),
                          "+f"(acc[mt][nt][2]), "+f"(acc[mt][nt][3])
                        : "r"(af[mt][0]), "r"(af[mt][1]), "r"(af[mt][2]), "r"(af[mt][3]),
                          "r"(bf[nt][0]), "r"(bf[nt][1]));
                }
            __syncthreads();

            if (t + 2 < nTiles) {
                int k0 = (t + 2) * BK;
                uint32_t off = st ? asBytes : 0;
                uint32_t offB = st ? bsBytes : 0;
                cp_async16(sa + off, aPtr + k0);
                cp_async16(sb + offB, bPtr + k0);
                cp_commit();
            }
        }

#pragma unroll
        for (int mt = 0; mt < 2; mt++) {
            int r0 = rowBase + mB + mt * 16 + g;
            int r1 = r0 + 8;
            float s0 = (r0 < M) ? scale[r0] : 1.0f;
            float s1 = (r1 < M) ? scale[r1] : 1.0f;
#pragma unroll
            for (int nt = 0; nt < 8; nt++) {
                int c = colBase + nB + nt * 8 + t4 * 2;
                if (r0 < M) {
                    __half2 p = __floats2half2_rn(acc[mt][nt][0] * s0, acc[mt][nt][1] * s0);
                    *reinterpret_cast<__half2*>(&Ch[(size_t)r0 * HID + c]) = p;
                }
                if (r1 < M) {
                    __half2 p = __floats2half2_rn(acc[mt][nt][2] * s1, acc[mt][nt][3] * s1);
                    *reinterpret_cast<__half2*>(&Ch[(size_t)r1 * HID + c]) = p;
                }
            }
        }
        __syncthreads();
    }
}

// ---------------- gather: pure row sums (messages pre-scaled) ----------------
// out[d] = relu(dinv[d] * (sum_{src} m[src] + m[d]) + b)
__global__ void gather_kernel(const __half* __restrict__ hp, __half* __restrict__ out,
                              const int* __restrict__ row_ptr, const int* __restrict__ csr_src,
                              const float* __restrict__ dinv, const float* __restrict__ bias, int n) {
    int warp = (blockIdx.x * blockDim.x + threadIdx.x) >> 5;
    int lane = threadIdx.x & 31;
    if (warp >= n) return;
    int beg = row_ptr[warp];
    int end = row_ptr[warp + 1];
    const int colOff = lane * 8;

    float a0[8], a1[8];
#pragma unroll
    for (int j = 0; j < 8; j++) { a0[j] = 0.f; a1[j] = 0.f; }

    int e = beg;
    for (; e + 8 <= end; e += 8) {
        int s[8];
#pragma unroll
        for (int q = 0; q < 8; q++) s[q] = csr_src[e + q];
        uint4 u[8];
#pragma unroll
        for (int q = 0; q < 8; q++)
            u[q] = __ldg(reinterpret_cast<const uint4*>(hp + (size_t)s[q] * HID + colOff));
#pragma unroll
        for (int q = 0; q < 8; q++) add_h16x8((q & 1) ? a1 : a0, u[q]);
    }
    if (e + 4 <= end) {
        int s[4];
#pragma unroll
        for (int q = 0; q < 4; q++) s[q] = csr_src[e + q];
        uint4 u[4];
#pragma unroll
        for (int q = 0; q < 4; q++)
            u[q] = __ldg(reinterpret_cast<const uint4*>(hp + (size_t)s[q] * HID + colOff));
#pragma unroll
        for (int q = 0; q < 4; q++) add_h16x8((q & 1) ? a1 : a0, u[q]);
        e += 4;
    }
    if (e + 2 <= end) {
        int s0 = csr_src[e];
        int s1 = csr_src[e + 1];
        uint4 u0 = __ldg(reinterpret_cast<const uint4*>(hp + (size_t)s0 * HID + colOff));
        uint4 u1 = __ldg(reinterpret_cast<const uint4*>(hp + (size_t)s1 * HID + colOff));
        add_h16x8(a0, u0);
        add_h16x8(a1, u1);
        e += 2;
    }
    if (e < end) {
        int s0 = csr_src[e];
        uint4 u0 = __ldg(reinterpret_cast<const uint4*>(hp + (size_t)s0 * HID + colOff));
        add_h16x8(a0, u0);
    }
    // self contribution (m[d] already pre-scaled)
    {
        uint4 u = *reinterpret_cast<const uint4*>(hp + (size_t)warp * HID + colOff);
        add_h16x8(a1, u);
    }

    float dvd = dinv[warp];
    float4 b0 = *reinterpret_cast<const float4*>(bias + colOff);
    float4 b1 = *reinterpret_cast<const float4*>(bias + colOff + 4);
    float o[8];
    o[0] = fmaxf(dvd * (a0[0] + a1[0]) + b0.x, 0.f);
    o[1] = fmaxf(dvd * (a0[1] + a1[1]) + b0.y, 0.f);
    o[2] = fmaxf(dvd * (a0[2] + a1[2]) + b0.z, 0.f);
    o[3] = fmaxf(dvd * (a0[3] + a1[3]) + b0.w, 0.f);
    o[4] = fmaxf(dvd * (a0[4] + a1[4]) + b1.x, 0.f);
    o[5] = fmaxf(dvd * (a0[5] + a1[5]) + b1.y, 0.f);
    o[6] = fmaxf(dvd * (a0[6] + a1[6]) + b1.z, 0.f);
    o[7] = fmaxf(dvd * (a0[7] + a1[7]) + b1.w, 0.f);

    uint4 packed;
    uint32_t* pw = reinterpret_cast<uint32_t*>(&packed);
#pragma unroll
    for (int q = 0; q < 4; q++) {
        __half2 p = __floats2half2_rn(o[2 * q], o[2 * q + 1]);
        pw[q] = *reinterpret_cast<uint32_t*>(&p);
    }
    *reinterpret_cast<uint4*>(out + (size_t)warp * HID + colOff) = packed;
}

// ---------------- fused pooling + output head (fp16 input) ----------------
__global__ void pool_out_kernel(const __half* __restrict__ h, const void* __restrict__ batch,
                                int n, const float* __restrict__ W, const float* __restrict__ b,
                                float* __restrict__ out) {
    __shared__ int sRange[2];
    __shared__ float sPool[HID];
    int g = blockIdx.x;
    int tid = threadIdx.x;
    if (tid < 2) {
        int target = g + tid;
        int is64 = g_is64;
        int lo = 0, hi = n;
        while (lo < hi) {
            int mid = (lo + hi) >> 1;
            if (get_idx(batch, mid, is64) < target) lo = mid + 1; else hi = mid;
        }
        sRange[tid] = lo;
    }
    __syncthreads();
    int beg = sRange[0];
    int end = sRange[1];
    float sum = 0.0f;
    for (int i = beg; i < end; i++) sum += __half2float(h[(size_t)i * HID + tid]);
    sPool[tid] = sum / fmaxf((float)(end - beg), 1.0f);
    __syncthreads();

    {
        int c = tid & 15;
        int k0 = (tid >> 4) * 16;
        float p = 0.0f;
#pragma unroll
        for (int k = 0; k < 16; k++) p += sPool[k0 + k] * W[(k0 + k) * NCLS + c];
        __shared__ float sAll[16][NCLS];
        sAll[tid >> 4][c] = p;
        __syncthreads();
        if (tid < NCLS) {
            float s = b[tid];
#pragma unroll
            for (int q = 0; q < 16; q++) s += sAll[q][tid];
            out[g * NCLS + tid] = s;
        }
    }
}

// ---------------- launch ----------------
extern "C" void kernel_launch(void* const* d_in, const int* in_sizes, int n_in,
                              void* d_out, int out_size) {
    const float* x     = (const float*)d_in[0];
    const void*  ei    = d_in[1];
    const void*  batch = d_in[2];
    const float* W_in  = (const float*)d_in[3];
    const float* b_in  = (const float*)d_in[4];
    const float* W1    = (const float*)d_in[5];
    const float* b1    = (const float*)d_in[6];
    const float* W2    = (const float*)d_in[7];
    const float* b2    = (const float*)d_in[8];
    const float* W_out = (const float*)d_in[9];
    const float* b_out = (const float*)d_in[10];

    const int N = in_sizes[0] / INDIM;
    const int E = in_sizes[1] / 2;

    float *dinv, *Wcomb, *bcomb;
    __half *bufH, *bufAh, *W2t;
    int *indeg, *row_ptr, *cursor, *csr_src, *localscan;
    cudaGetSymbolAddress((void**)&bufH, g_bufH);
    cudaGetSymbolAddress((void**)&bufAh, g_bufAh);
    cudaGetSymbolAddress((void**)&W2t, g_W2t);
    cudaGetSymbolAddress((void**)&Wcomb, g_Wcomb);
    cudaGetSymbolAddress((void**)&bcomb, g_bcomb);
    cudaGetSymbolAddress((void**)&dinv, g_dinv);
    cudaGetSymbolAddress((void**)&indeg, g_indeg);
    cudaGetSymbolAddress((void**)&row_ptr, g_row_ptr);
    cudaGetSymbolAddress((void**)&cursor, g_cursor);
    cudaGetSymbolAddress((void**)&csr_src, g_csr_src);
    cudaGetSymbolAddress((void**)&localscan, g_localscan);

    static cudaStream_t sSide = nullptr;
    static cudaEvent_t evFork = nullptr, evJoin = nullptr;
    if (sSide == nullptr) {
        cudaStreamCreateWithFlags(&sSide, cudaStreamNonBlocking);
        cudaEventCreateWithFlags(&evFork, cudaEventDisableTiming);
        cudaEventCreateWithFlags(&evJoin, cudaEventDisableTiming);
    }

    const int GEMM_GRID = 296;

    // ---- fork: preprocessing on side stream ----
    cudaEventRecord(evFork, 0);
    cudaStreamWaitEvent(sSide, evFork, 0);

    cudaMemsetAsync(indeg, 0, N * sizeof(int), sSide);
    hist_dst_kernel<<<(E + 255) / 256, 256, 0, sSide>>>(ei, E, indeg);
    const int nb = (N + 1023) / 1024;
    scan_local_kernel<<<nb, 1024, 0, sSide>>>(indeg, localscan, N);
    scan_finalize_kernel<<<(N + 255) / 256, 256, 0, sSide>>>(indeg, localscan, row_ptr, cursor, dinv, N);
    fill_csr_kernel<<<(E + 255) / 256, 256, 0, sSide>>>(ei, E, cursor, csr_src);
    cudaEventRecord(evJoin, sSide);

    // ---- main stream ----
    {
        dim3 tb(32, 32);
        dim3 tg(HID / 32, HID / 32);
        transpose_w2_kernel<<<tg, tb>>>(W2, W2t);
    }
    weight_combine_kernel<<<INDIM + 1, HID>>>(W_in, b_in, W1, Wcomb, bcomb);
    tf32gemm_kernel<<<GEMM_GRID, 256>>>(x, Wcomb, bufH, N, INDIM, bcomb);

    cudaStreamWaitEvent(0, evJoin, 0);

    // pre-scale layer-1 messages by dinv[src]
    scale_rows_kernel<<<(N * (HID / 8) + 255) / 256, 256>>>(bufH, dinv, N);

    gather_kernel<<<(N * 32 + 255) / 256, 256>>>(bufH, bufAh, row_ptr, csr_src, dinv, b1, N);
    f16gemm_kernel<<<GEMM_GRID, 256>>>(bufAh, W2t, bufH, N, dinv);   // epilogue pre-scales layer-2 messages
    gather_kernel<<<(N * 32 + 255) / 256, 256>>>(bufH, bufAh, row_ptr, csr_src, dinv, b2, N);

    pool_out_kernel<<<NGRAPH, HID>>>(bufAh, batch, N, W_out, b_out, (float*)d_out);
}